// round 14
// baseline (speedup 1.0000x reference)
#include <cuda_runtime.h>
#include <math.h>
#include <stdint.h>

// Problem constants
#define B 2
#define S 2048
#define D 1024
#define H 16
#define HD 64
#define MASK_VALUE -1000000.0f
#define BSD (B * S * D)            // 4194304

// Scratch (static device globals — no allocation allowed)
__device__ float g_q[BSD];         // Q-projection output (fp32)
__device__ float g_k[BSD];         // K-projection output (tf32-rounded)
__device__ float g_v[BSD];         // V-projection output (tf32-rounded)
__device__ float g_attn[BSD];      // attention output (tf32-rounded)
__device__ float g_qr[BSD];        // tf32-rounded input activations
__device__ float g_kr[BSD];
__device__ float g_vr[BSD];
__device__ float g_wr[4 * D * D];  // tf32-rounded weights, row-major [K][N]

// ===========================================================================
// Helpers
// ===========================================================================
static __device__ __forceinline__ uint32_t smem_u32(const void* p) {
    uint32_t a;
    asm("{ .reg .u64 t; cvta.to.shared.u64 t, %1; cvt.u32.u64 %0, t; }"
        : "=r"(a) : "l"(p));
    return a;
}
static __device__ __forceinline__ uint32_t f2tf32(float x) {
    uint32_t r;
    asm("cvt.rna.tf32.f32 %0, %1;" : "=r"(r) : "f"(x));
    return r;
}
static __device__ __forceinline__ float rnd_tf32(float x) {
    return __uint_as_float(f2tf32(x));
}
static __device__ __forceinline__ float ex2(float x) {
    float r;
    asm("ex2.approx.f32 %0, %1;" : "=f"(r) : "f"(x));
    return r;
}
static __device__ __forceinline__ void cp_async16(uint32_t smem, const void* gmem) {
    asm volatile("cp.async.ca.shared.global [%0], [%1], 16;"
                 :: "r"(smem), "l"(gmem) : "memory");
}
static __device__ __forceinline__ void cp_commit() {
    asm volatile("cp.async.commit_group;" ::: "memory");
}
static __device__ __forceinline__ void mma_tf32(
    float d[4], const uint32_t a[4], uint32_t b0, uint32_t b1)
{
    asm volatile(
        "mma.sync.aligned.m16n8k8.row.col.f32.tf32.tf32.f32 "
        "{%0,%1,%2,%3}, {%4,%5,%6,%7}, {%8,%9}, {%0,%1,%2,%3};"
        : "+f"(d[0]), "+f"(d[1]), "+f"(d[2]), "+f"(d[3])
        : "r"(a[0]), "r"(a[1]), "r"(a[2]), "r"(a[3]), "r"(b0), "r"(b1));
}

// ===========================================================================
// Prep: tf32-round activations and weights (elementwise, float4)
// ===========================================================================
__global__ __launch_bounds__(256) void prep_acts(
    const float* __restrict__ Q, const float* __restrict__ K,
    const float* __restrict__ V)
{
    const int z = blockIdx.z;
    const float* src = (z == 0) ? Q : (z == 1) ? K : V;
    float* dst = (z == 0) ? g_qr : (z == 1) ? g_kr : g_vr;
    size_t i = ((size_t)blockIdx.x * 256 + threadIdx.x) * 4;
    float4 t = *(const float4*)(src + i);
    t.x = rnd_tf32(t.x); t.y = rnd_tf32(t.y);
    t.z = rnd_tf32(t.z); t.w = rnd_tf32(t.w);
    *(float4*)(dst + i) = t;
}

__global__ __launch_bounds__(256) void prep_w(
    const float* __restrict__ Wq, const float* __restrict__ Wk,
    const float* __restrict__ Wv, const float* __restrict__ Wo)
{
    const int z = blockIdx.z;
    const float* src = (z == 0) ? Wq : (z == 1) ? Wk : (z == 2) ? Wv : Wo;
    float* dst = g_wr + (size_t)z * D * D;
    size_t i = ((size_t)blockIdx.x * 256 + threadIdx.x) * 4;
    float4 t = *(const float4*)(src + i);
    t.x = rnd_tf32(t.x); t.y = rnd_tf32(t.y);
    t.z = rnd_tf32(t.z); t.w = rnd_tf32(t.w);
    *(float4*)(dst + i) = t;
}

// ===========================================================================
// tf32 mma.sync GEMM: C[M,N] = A[M,K] @ Bm[K,N].
// 128x128 CTA tile, BK=32, 4 warps (64x64 each), 2-stage cp.async.
// *** 3 CTAs/SM *** (71.7KB smem x3 = 215KB; regs capped ~170 by bounds).
// ===========================================================================
#define APITCH 36
#define BP 136
#define ATILE_F (128 * APITCH)
#define BTILE_F (32 * BP)
#define GEMM_SMEM_BYTES ((2 * ATILE_F + 2 * BTILE_F) * 4)   // 71680

static __device__ __forceinline__ void gemm_load_tile(
    uint32_t sA, uint32_t sB, const float* Ab, const float* Bm,
    int bn, int kc, int tid)
{
#pragma unroll
    for (int t = 0; t < 8; t++) {
        int idx = tid + (t << 7);
        int ar = idx >> 3, ac = idx & 7;
        cp_async16(sA + (uint32_t)(ar * APITCH + ac * 4) * 4,
                   Ab + (size_t)ar * D + kc * 32 + ac * 4);
        int br = idx >> 5, bc = idx & 31;
        cp_async16(sB + (uint32_t)(br * BP + bc * 4) * 4,
                   Bm + (size_t)(kc * 32 + br) * D + bn + bc * 4);
    }
}

static __device__ __forceinline__ void gemm_core(
    const float* __restrict__ A, const float* __restrict__ Bm,
    float* __restrict__ C, bool round_out)
{
    extern __shared__ float smf[];
    float* bufA[2] = { smf,              smf + ATILE_F };
    float* bufB[2] = { smf + 2 * ATILE_F, smf + 2 * ATILE_F + BTILE_F };
    uint32_t uA[2] = { smem_u32(bufA[0]), smem_u32(bufA[1]) };
    uint32_t uB[2] = { smem_u32(bufB[0]), smem_u32(bufB[1]) };

    const int tid = threadIdx.x;
    const int wid = tid >> 5;
    const int lane = tid & 31;
    const int g  = lane >> 2;
    const int tg = lane & 3;
    const int wm = wid & 1;
    const int wn = wid >> 1;

    const int bm = blockIdx.y * 128;
    const int bn = blockIdx.x * 128;
    const float* Ab = A + (size_t)bm * D;

    float d[4][8][4];
#pragma unroll
    for (int mi = 0; mi < 4; mi++)
#pragma unroll
        for (int ni = 0; ni < 8; ni++)
#pragma unroll
            for (int r = 0; r < 4; r++) d[mi][ni][r] = 0.f;

    gemm_load_tile(uA[0], uB[0], Ab, Bm, bn, 0, tid);
    cp_commit();

    for (int kc = 0; kc < D / 32; kc++) {
        const int buf = kc & 1;
        if (kc + 1 < D / 32) {
            gemm_load_tile(uA[buf ^ 1], uB[buf ^ 1], Ab, Bm, bn, kc + 1, tid);
            cp_commit();
            asm volatile("cp.async.wait_group 1;" ::: "memory");
        } else {
            asm volatile("cp.async.wait_group 0;" ::: "memory");
        }
        __syncthreads();

        const float* As = bufA[buf];
        const float* Bs = bufB[buf];
#pragma unroll
        for (int ks = 0; ks < 4; ks++) {
            const int k0 = ks * 8;
            uint32_t af[4][4];
#pragma unroll
            for (int mi = 0; mi < 4; mi++) {
                int r = wm * 64 + mi * 16 + g;
                af[mi][0] = __float_as_uint(As[r * APITCH + k0 + tg]);
                af[mi][1] = __float_as_uint(As[(r + 8) * APITCH + k0 + tg]);
                af[mi][2] = __float_as_uint(As[r * APITCH + k0 + tg + 4]);
                af[mi][3] = __float_as_uint(As[(r + 8) * APITCH + k0 + tg + 4]);
            }
#pragma unroll
            for (int ni = 0; ni < 8; ni++) {
                int col = wn * 64 + ni * 8 + g;
                uint32_t b0 = __float_as_uint(Bs[(k0 + tg) * BP + col]);
                uint32_t b1 = __float_as_uint(Bs[(k0 + tg + 4) * BP + col]);
#pragma unroll
                for (int mi = 0; mi < 4; mi++)
                    mma_tf32(d[mi][ni], af[mi], b0, b1);
            }
        }
        __syncthreads();
    }

#pragma unroll
    for (int mi = 0; mi < 4; mi++) {
        int row = bm + wm * 64 + mi * 16 + g;
#pragma unroll
        for (int ni = 0; ni < 8; ni++) {
            int col = bn + wn * 64 + ni * 8 + tg * 2;
            float v0 = d[mi][ni][0], v1 = d[mi][ni][1];
            float v2 = d[mi][ni][2], v3 = d[mi][ni][3];
            if (round_out) {
                v0 = rnd_tf32(v0); v1 = rnd_tf32(v1);
                v2 = rnd_tf32(v2); v3 = rnd_tf32(v3);
            }
            *(float2*)(&C[(size_t)row * D + col]) = make_float2(v0, v1);
            *(float2*)(&C[(size_t)(row + 8) * D + col]) = make_float2(v2, v3);
        }
    }
}

__global__ __launch_bounds__(128, 3) void gemm_qkv()
{
    const int z = blockIdx.z;
    const float* A = (z == 0) ? g_qr : (z == 1) ? g_kr : g_vr;
    const float* Bm = g_wr + (size_t)z * D * D;
    float* C = (z == 0) ? g_q : (z == 1) ? g_k : g_v;
    gemm_core(A, Bm, C, z > 0);
}

__global__ __launch_bounds__(128, 3) void gemm_out(float* __restrict__ C)
{
    gemm_core(g_attn, g_wr + (size_t)3 * D * D, C, false);
}

// ===========================================================================
// Tensor-core flash attention (R11 structure + log2-domain ex2 softmax +
// Ps aliased onto Qs). CTA = 128 query rows of one (b,h); 8 warps.
// Q fragments (tf32 hi/lo split, pre-scaled by 0.125*log2e) in registers.
// 3 K/V buffers -> one __syncthreads per tile. K/V pre-rounded tf32.
// Ps occupies the Qs region (Qs dead after the register hoist; each warp's
// Pw rows == the Qs rows only that warp read during its own hoist).
// P rounded to tf32 before row-sum (cancels in O = PV/l). Masked tiles
// skipped; vlen==0 processes all (mask path) -> uniform softmax.
// ===========================================================================
#define BQ 128
#define BKT 64
#define QP 68
#define KP 72
#define PP 68
#define NKV 3
#define AT_SMEM_F (BQ * QP + 2 * NKV * BKT * KP)
#define AT_SMEM_BYTES (AT_SMEM_F * 4)      // 145408

__global__ __launch_bounds__(256, 1) void attn_mma(
    const int* __restrict__ valid, float* __restrict__ out)
{
    extern __shared__ float sm[];
    float* Qs = sm;                          // [128][QP]; reused as Ps
    float* Ks = Qs + BQ * QP;                // NKV x [64][KP]
    float* Vs = Ks + NKV * BKT * KP;         // NKV x [64][KP]
    float* Ps = Qs;                          // alias (8 x [16][PP] == 128xQP)
    const uint32_t uKs = smem_u32(Ks);
    const uint32_t uVs = smem_u32(Vs);

    const int tid  = threadIdx.x;
    const int wid  = tid >> 5;
    const int lane = tid & 31;
    const int g    = lane >> 2;
    const int tg   = lane & 3;
    const int bh = blockIdx.y;
    const int b  = bh / H;
    const int h  = bh % H;
    const int q0 = blockIdx.x * BQ;
    const int vlen = valid[b];
    const float qscale = 0.125f * 1.4426950408889634f;   // scale * log2(e)

    const float* qbase = g_q + (size_t)b * S * D + (size_t)h * HD;
    const float* kbase = g_k + (size_t)b * S * D + (size_t)h * HD;
    const float* vbase = g_v + (size_t)b * S * D + (size_t)h * HD;

    // Stage Q tile
#pragma unroll
    for (int t = 0; t < 8; t++) {
        int idx = tid + t * 256;
        int row = idx >> 4;
        int c   = idx & 15;
        float4 tq = *(const float4*)(qbase + (size_t)(q0 + row) * D + c * 4);
        float* dq = &Qs[row * QP + c * 4];
        dq[0] = tq.x; dq[1] = tq.y; dq[2] = tq.z; dq[3] = tq.w;
    }
    // Preload K/V tile 0 into buffer 0
    {
#pragma unroll
        for (int t = 0; t < 4; t++) {
            int idx = tid + t * 256;
            int row = idx >> 4;
            int c   = idx & 15;
            uint32_t off = (uint32_t)(row * KP + c * 4) * 4;
            cp_async16(uKs + off, kbase + (size_t)row * D + c * 4);
            cp_async16(uVs + off, vbase + (size_t)row * D + c * 4);
        }
        cp_commit();
    }
    __syncthreads();   // Qs visible

    const int r0 = wid * 16;
    uint32_t qh[8][4], ql[8][4];
#pragma unroll
    for (int ks = 0; ks < 8; ks++) {
        const int k0 = ks * 8;
        float qf[4];
        qf[0] = qscale * Qs[(r0 + g) * QP + k0 + tg];
        qf[1] = qscale * Qs[(r0 + g + 8) * QP + k0 + tg];
        qf[2] = qscale * Qs[(r0 + g) * QP + k0 + tg + 4];
        qf[3] = qscale * Qs[(r0 + g + 8) * QP + k0 + tg + 4];
#pragma unroll
        for (int i = 0; i < 4; i++) {
            qh[ks][i] = f2tf32(qf[i]);
            ql[ks][i] = f2tf32(qf[i] - __uint_as_float(qh[ks][i]));
        }
    }

    float o[8][4];
#pragma unroll
    for (int ni = 0; ni < 8; ni++)
#pragma unroll
        for (int c = 0; c < 4; c++) o[ni][c] = 0.f;
    float m0 = -INFINITY, m1 = -INFINITY, l0 = 0.f, l1 = 0.f;

    const int nk = (vlen == 0) ? (S / BKT) : ((vlen + BKT - 1) / BKT);
    float* Pw = Ps + wid * 16 * PP;   // same rows this warp hoisted from

    for (int kt = 0; kt < nk; kt++) {
        const int buf = kt % NKV;
        const int kr0 = kt * BKT;
        if (kt + 1 < nk) {
            const int nr0 = (kt + 1) * BKT;
            const uint32_t bo = (uint32_t)(((kt + 1) % NKV) * BKT * KP) * 4;
#pragma unroll
            for (int t = 0; t < 4; t++) {
                int idx = tid + t * 256;
                int row = idx >> 4;
                int c   = idx & 15;
                uint32_t off = bo + (uint32_t)(row * KP + c * 4) * 4;
                cp_async16(uKs + off, kbase + (size_t)(nr0 + row) * D + c * 4);
                cp_async16(uVs + off, vbase + (size_t)(nr0 + row) * D + c * 4);
            }
            cp_commit();
            asm volatile("cp.async.wait_group 1;" ::: "memory");
        } else {
            asm volatile("cp.async.wait_group 0;" ::: "memory");
        }
        __syncthreads();   // tile kt ready; bounds warp skew to 1 iteration

        const float* Kb = Ks + buf * BKT * KP;
        const float* Vb = Vs + buf * BKT * KP;

        // ---- S(log2) = (Q*qscale) @ K^T (2-MMA tf32 split) ----
        float sc[8][4];
#pragma unroll
        for (int ni = 0; ni < 8; ni++)
#pragma unroll
            for (int c = 0; c < 4; c++) sc[ni][c] = 0.f;

#pragma unroll
        for (int ks = 0; ks < 8; ks++) {
            const int k0 = ks * 8;
#pragma unroll
            for (int ni = 0; ni < 8; ni++) {
                const float* kr = &Kb[(ni * 8 + g) * KP + k0];
                uint32_t b0 = __float_as_uint(kr[tg]);
                uint32_t b1 = __float_as_uint(kr[tg + 4]);
                mma_tf32(sc[ni], qh[ks], b0, b1);
                mma_tf32(sc[ni], ql[ks], b0, b1);
            }
        }

        // ---- mask (boundary/empty tiles only) + online softmax (log2) ----
        if (kr0 + BKT > vlen) {
#pragma unroll
            for (int ni = 0; ni < 8; ni++) {
                int col = kr0 + ni * 8 + 2 * tg;
                bool v0 = col < vlen, v1 = (col + 1) < vlen;
                sc[ni][0] = v0 ? sc[ni][0] : MASK_VALUE;
                sc[ni][1] = v1 ? sc[ni][1] : MASK_VALUE;
                sc[ni][2] = v0 ? sc[ni][2] : MASK_VALUE;
                sc[ni][3] = v1 ? sc[ni][3] : MASK_VALUE;
            }
        }

        float mn0 = m0, mn1 = m1;
#pragma unroll
        for (int ni = 0; ni < 8; ni++) {
            mn0 = fmaxf(mn0, fmaxf(sc[ni][0], sc[ni][1]));
            mn1 = fmaxf(mn1, fmaxf(sc[ni][2], sc[ni][3]));
        }
        mn0 = fmaxf(mn0, __shfl_xor_sync(0xffffffffu, mn0, 1));
        mn0 = fmaxf(mn0, __shfl_xor_sync(0xffffffffu, mn0, 2));
        mn1 = fmaxf(mn1, __shfl_xor_sync(0xffffffffu, mn1, 1));
        mn1 = fmaxf(mn1, __shfl_xor_sync(0xffffffffu, mn1, 2));

        float a0 = ex2(m0 - mn0);
        float a1 = ex2(m1 - mn1);
        m0 = mn0; m1 = mn1;

        float rs0 = 0.f, rs1 = 0.f;
#pragma unroll
        for (int ni = 0; ni < 8; ni++) {
            float p0 = rnd_tf32(ex2(sc[ni][0] - mn0));
            float p1 = rnd_tf32(ex2(sc[ni][1] - mn0));
            float p2 = rnd_tf32(ex2(sc[ni][2] - mn1));
            float p3 = rnd_tf32(ex2(sc[ni][3] - mn1));
            rs0 += p0 + p1;
            rs1 += p2 + p3;
            *(float2*)(&Pw[g * PP + ni * 8 + 2 * tg])       = make_float2(p0, p1);
            *(float2*)(&Pw[(g + 8) * PP + ni * 8 + 2 * tg]) = make_float2(p2, p3);
        }
        rs0 += __shfl_xor_sync(0xffffffffu, rs0, 1);
        rs0 += __shfl_xor_sync(0xffffffffu, rs0, 2);
        rs1 += __shfl_xor_sync(0xffffffffu, rs1, 1);
        rs1 += __shfl_xor_sync(0xffffffffu, rs1, 2);
        l0 = l0 * a0 + rs0;
        l1 = l1 * a1 + rs1;

#pragma unroll
        for (int ni = 0; ni < 8; ni++) {
            o[ni][0] *= a0; o[ni][1] *= a0;
            o[ni][2] *= a1; o[ni][3] *= a1;
        }
        __syncwarp();

        // ---- O += P @ V (both tf32) ----
#pragma unroll
        for (int ks = 0; ks < 8; ks++) {
            const int k0 = ks * 8;
            uint32_t pa[4];
            pa[0] = __float_as_uint(Pw[g * PP + k0 + tg]);
            pa[1] = __float_as_uint(Pw[(g + 8) * PP + k0 + tg]);
            pa[2] = __float_as_uint(Pw[g * PP + k0 + tg + 4]);
            pa[3] = __float_as_uint(Pw[(g + 8) * PP + k0 + tg + 4]);
#pragma unroll
            for (int ni = 0; ni < 8; ni++) {
                uint32_t b0 = __float_as_uint(Vb[(k0 + tg) * KP + ni * 8 + g]);
                uint32_t b1 = __float_as_uint(Vb[(k0 + tg + 4) * KP + ni * 8 + g]);
                mma_tf32(o[ni], pa, b0, b1);
            }
        }
        __syncwarp();
        // no end-of-tile __syncthreads: 3-buffer rotation keeps the
        // next prefetch target disjoint from any in-use buffer
    }

    // Epilogue: normalize + round to tf32 (feeds gemm_out's raw loads)
    float inv0 = 1.f / l0, inv1 = 1.f / l1;
    int row0 = q0 + r0 + g;
#pragma unroll
    for (int ni = 0; ni < 8; ni++) {
        int col = h * HD + ni * 8 + 2 * tg;
        *(float2*)(&out[((size_t)b * S + row0) * D + col]) =
            make_float2(rnd_tf32(o[ni][0] * inv0), rnd_tf32(o[ni][1] * inv0));
        *(float2*)(&out[((size_t)b * S + row0 + 8) * D + col]) =
            make_float2(rnd_tf32(o[ni][2] * inv1), rnd_tf32(o[ni][3] * inv1));
    }
}

// ===========================================================================
// Launch
// ===========================================================================
extern "C" void kernel_launch(void* const* d_in, const int* in_sizes, int n_in,
                              void* d_out, int out_size)
{
    const float* Q  = (const float*)d_in[0];
    const float* K  = (const float*)d_in[1];
    const float* V  = (const float*)d_in[2];
    const int* valid = (const int*)d_in[3];
    const float* Wq = (const float*)d_in[4];
    const float* Wk = (const float*)d_in[5];
    const float* Wv = (const float*)d_in[6];
    const float* Wo = (const float*)d_in[7];
    float* out = (float*)d_out;

    float* ga;
    cudaGetSymbolAddress((void**)&ga, g_attn);

    cudaFuncSetAttribute(gemm_qkv, cudaFuncAttributeMaxDynamicSharedMemorySize,
                         GEMM_SMEM_BYTES);
    cudaFuncSetAttribute(gemm_out, cudaFuncAttributeMaxDynamicSharedMemorySize,
                         GEMM_SMEM_BYTES);
    cudaFuncSetAttribute(attn_mma, cudaFuncAttributeMaxDynamicSharedMemorySize,
                         AT_SMEM_BYTES);

    prep_acts<<<dim3(BSD / 4 / 256, 1, 3), 256>>>(Q, K, V);
    prep_w<<<dim3(D * D / 4 / 256, 1, 4), 256>>>(Wq, Wk, Wv, Wo);

    gemm_qkv<<<dim3(D / 128, (B * S) / 128, 3), 128, GEMM_SMEM_BYTES>>>();

    attn_mma<<<dim3(S / BQ, B * H), 256, AT_SMEM_BYTES>>>(valid, ga);

    gemm_out<<<dim3(D / 128, (B * S) / 128), 128, GEMM_SMEM_BYTES>>>(out);
}

// round 17
// speedup vs baseline: 1.0349x; 1.0349x over previous
#include <cuda_runtime.h>
#include <math.h>
#include <stdint.h>

// Problem constants
#define B 2
#define S 2048
#define D 1024
#define H 16
#define HD 64
#define MASK_VALUE -1000000.0f
#define BSD (B * S * D)            // 4194304

// Scratch (static device globals — no allocation allowed)
__device__ float g_q[BSD];         // Q-projection output (fp32)
__device__ float g_k[BSD];         // K-projection output (tf32-rounded)
__device__ float g_v[BSD];         // V-projection output (tf32-rounded)
__device__ float g_attn[BSD];      // attention output (tf32-rounded)
__device__ float g_qr[BSD];        // tf32-rounded input activations
__device__ float g_kr[BSD];
__device__ float g_vr[BSD];
__device__ float g_wr[4 * D * D];  // tf32-rounded weights, row-major [K][N]

// ===========================================================================
// Helpers
// ===========================================================================
static __device__ __forceinline__ uint32_t smem_u32(const void* p) {
    uint32_t a;
    asm("{ .reg .u64 t; cvta.to.shared.u64 t, %1; cvt.u32.u64 %0, t; }"
        : "=r"(a) : "l"(p));
    return a;
}
static __device__ __forceinline__ uint32_t f2tf32(float x) {
    uint32_t r;
    asm("cvt.rna.tf32.f32 %0, %1;" : "=r"(r) : "f"(x));
    return r;
}
static __device__ __forceinline__ float rnd_tf32(float x) {
    return __uint_as_float(f2tf32(x));
}
static __device__ __forceinline__ float ex2(float x) {
    float r;
    asm("ex2.approx.f32 %0, %1;" : "=f"(r) : "f"(x));
    return r;
}
static __device__ __forceinline__ void cp_async16(uint32_t smem, const void* gmem) {
    asm volatile("cp.async.ca.shared.global [%0], [%1], 16;"
                 :: "r"(smem), "l"(gmem) : "memory");
}
static __device__ __forceinline__ void cp_commit() {
    asm volatile("cp.async.commit_group;" ::: "memory");
}
static __device__ __forceinline__ void mma_tf32(
    float d[4], const uint32_t a[4], uint32_t b0, uint32_t b1)
{
    asm volatile(
        "mma.sync.aligned.m16n8k8.row.col.f32.tf32.tf32.f32 "
        "{%0,%1,%2,%3}, {%4,%5,%6,%7}, {%8,%9}, {%0,%1,%2,%3};"
        : "+f"(d[0]), "+f"(d[1]), "+f"(d[2]), "+f"(d[3])
        : "r"(a[0]), "r"(a[1]), "r"(a[2]), "r"(a[3]), "r"(b0), "r"(b1));
}

// ===========================================================================
// Prep: tf32-round activations and weights (elementwise, float4)
// ===========================================================================
__global__ __launch_bounds__(256) void prep_acts(
    const float* __restrict__ Q, const float* __restrict__ K,
    const float* __restrict__ V)
{
    const int z = blockIdx.z;
    const float* src = (z == 0) ? Q : (z == 1) ? K : V;
    float* dst = (z == 0) ? g_qr : (z == 1) ? g_kr : g_vr;
    size_t i = ((size_t)blockIdx.x * 256 + threadIdx.x) * 4;
    float4 t = *(const float4*)(src + i);
    t.x = rnd_tf32(t.x); t.y = rnd_tf32(t.y);
    t.z = rnd_tf32(t.z); t.w = rnd_tf32(t.w);
    *(float4*)(dst + i) = t;
}

__global__ __launch_bounds__(256) void prep_w(
    const float* __restrict__ Wq, const float* __restrict__ Wk,
    const float* __restrict__ Wv, const float* __restrict__ Wo)
{
    const int z = blockIdx.z;
    const float* src = (z == 0) ? Wq : (z == 1) ? Wk : (z == 2) ? Wv : Wo;
    float* dst = g_wr + (size_t)z * D * D;
    size_t i = ((size_t)blockIdx.x * 256 + threadIdx.x) * 4;
    float4 t = *(const float4*)(src + i);
    t.x = rnd_tf32(t.x); t.y = rnd_tf32(t.y);
    t.z = rnd_tf32(t.z); t.w = rnd_tf32(t.w);
    *(float4*)(dst + i) = t;
}

// ===========================================================================
// tf32 mma.sync GEMM (R11 config): C[M,N] = A[M,K] @ Bm[K,N].
// 128x128 CTA tile, BK=32, 4 warps (64x64 each), 2-stage cp.async,
// 71.7KB smem -> 2 CTAs/SM, no register cap.
// ===========================================================================
#define APITCH 36
#define BP 136
#define ATILE_F (128 * APITCH)
#define BTILE_F (32 * BP)
#define GEMM_SMEM_BYTES ((2 * ATILE_F + 2 * BTILE_F) * 4)   // 71680

static __device__ __forceinline__ void gemm_load_tile(
    uint32_t sA, uint32_t sB, const float* Ab, const float* Bm,
    int bn, int kc, int tid)
{
#pragma unroll
    for (int t = 0; t < 8; t++) {
        int idx = tid + (t << 7);
        int ar = idx >> 3, ac = idx & 7;
        cp_async16(sA + (uint32_t)(ar * APITCH + ac * 4) * 4,
                   Ab + (size_t)ar * D + kc * 32 + ac * 4);
        int br = idx >> 5, bc = idx & 31;
        cp_async16(sB + (uint32_t)(br * BP + bc * 4) * 4,
                   Bm + (size_t)(kc * 32 + br) * D + bn + bc * 4);
    }
}

static __device__ __forceinline__ void gemm_core(
    const float* __restrict__ A, const float* __restrict__ Bm,
    float* __restrict__ C, bool round_out)
{
    extern __shared__ float smf[];
    float* bufA[2] = { smf,              smf + ATILE_F };
    float* bufB[2] = { smf + 2 * ATILE_F, smf + 2 * ATILE_F + BTILE_F };
    uint32_t uA[2] = { smem_u32(bufA[0]), smem_u32(bufA[1]) };
    uint32_t uB[2] = { smem_u32(bufB[0]), smem_u32(bufB[1]) };

    const int tid = threadIdx.x;
    const int wid = tid >> 5;
    const int lane = tid & 31;
    const int g  = lane >> 2;
    const int tg = lane & 3;
    const int wm = wid & 1;
    const int wn = wid >> 1;

    const int bm = blockIdx.y * 128;
    const int bn = blockIdx.x * 128;
    const float* Ab = A + (size_t)bm * D;

    float d[4][8][4];
#pragma unroll
    for (int mi = 0; mi < 4; mi++)
#pragma unroll
        for (int ni = 0; ni < 8; ni++)
#pragma unroll
            for (int r = 0; r < 4; r++) d[mi][ni][r] = 0.f;

    gemm_load_tile(uA[0], uB[0], Ab, Bm, bn, 0, tid);
    cp_commit();

    for (int kc = 0; kc < D / 32; kc++) {
        const int buf = kc & 1;
        if (kc + 1 < D / 32) {
            gemm_load_tile(uA[buf ^ 1], uB[buf ^ 1], Ab, Bm, bn, kc + 1, tid);
            cp_commit();
            asm volatile("cp.async.wait_group 1;" ::: "memory");
        } else {
            asm volatile("cp.async.wait_group 0;" ::: "memory");
        }
        __syncthreads();

        const float* As = bufA[buf];
        const float* Bs = bufB[buf];
#pragma unroll
        for (int ks = 0; ks < 4; ks++) {
            const int k0 = ks * 8;
            uint32_t af[4][4];
#pragma unroll
            for (int mi = 0; mi < 4; mi++) {
                int r = wm * 64 + mi * 16 + g;
                af[mi][0] = __float_as_uint(As[r * APITCH + k0 + tg]);
                af[mi][1] = __float_as_uint(As[(r + 8) * APITCH + k0 + tg]);
                af[mi][2] = __float_as_uint(As[r * APITCH + k0 + tg + 4]);
                af[mi][3] = __float_as_uint(As[(r + 8) * APITCH + k0 + tg + 4]);
            }
#pragma unroll
            for (int ni = 0; ni < 8; ni++) {
                int col = wn * 64 + ni * 8 + g;
                uint32_t b0 = __float_as_uint(Bs[(k0 + tg) * BP + col]);
                uint32_t b1 = __float_as_uint(Bs[(k0 + tg + 4) * BP + col]);
#pragma unroll
                for (int mi = 0; mi < 4; mi++)
                    mma_tf32(d[mi][ni], af[mi], b0, b1);
            }
        }
        __syncthreads();
    }

#pragma unroll
    for (int mi = 0; mi < 4; mi++) {
        int row = bm + wm * 64 + mi * 16 + g;
#pragma unroll
        for (int ni = 0; ni < 8; ni++) {
            int col = bn + wn * 64 + ni * 8 + tg * 2;
            float v0 = d[mi][ni][0], v1 = d[mi][ni][1];
            float v2 = d[mi][ni][2], v3 = d[mi][ni][3];
            if (round_out) {
                v0 = rnd_tf32(v0); v1 = rnd_tf32(v1);
                v2 = rnd_tf32(v2); v3 = rnd_tf32(v3);
            }
            *(float2*)(&C[(size_t)row * D + col]) = make_float2(v0, v1);
            *(float2*)(&C[(size_t)(row + 8) * D + col]) = make_float2(v2, v3);
        }
    }
}

__global__ __launch_bounds__(128, 2) void gemm_qkv()
{
    const int z = blockIdx.z;
    const float* A = (z == 0) ? g_qr : (z == 1) ? g_kr : g_vr;
    const float* Bm = g_wr + (size_t)z * D * D;
    float* C = (z == 0) ? g_q : (z == 1) ? g_k : g_v;
    gemm_core(A, Bm, C, z > 0);
}

__global__ __launch_bounds__(128, 2) void gemm_out(float* __restrict__ C)
{
    gemm_core(g_attn, g_wr + (size_t)3 * D * D, C, false);
}

// ===========================================================================
// Tensor-core flash attention (R14 version, measured 148.8us).
// CTA = 128 query rows of one (b,h); 8 warps. Q fragments (tf32 hi/lo split,
// pre-scaled by 0.125*log2e) in registers. 3 K/V buffers -> one
// __syncthreads per tile. K/V pre-rounded tf32. Ps aliased onto Qs (dead
// after hoist; each warp's Pw rows == the Qs rows only that warp read).
// log2-domain softmax with raw ex2. P rounded to tf32 before row-sum
// (cancels in O = PV/l). Masked tiles skipped; vlen==0 processes all.
// ===========================================================================
#define BQ 128
#define BKT 64
#define QP 68
#define KP 72
#define PP 68
#define NKV 3
#define AT_SMEM_F (BQ * QP + 2 * NKV * BKT * KP)
#define AT_SMEM_BYTES (AT_SMEM_F * 4)      // 145408

__global__ __launch_bounds__(256, 1) void attn_mma(
    const int* __restrict__ valid, float* __restrict__ out)
{
    extern __shared__ float sm[];
    float* Qs = sm;                          // [128][QP]; reused as Ps
    float* Ks = Qs + BQ * QP;                // NKV x [64][KP]
    float* Vs = Ks + NKV * BKT * KP;         // NKV x [64][KP]
    float* Ps = Qs;                          // alias
    const uint32_t uKs = smem_u32(Ks);
    const uint32_t uVs = smem_u32(Vs);

    const int tid  = threadIdx.x;
    const int wid  = tid >> 5;
    const int lane = tid & 31;
    const int g    = lane >> 2;
    const int tg   = lane & 3;
    const int bh = blockIdx.y;
    const int b  = bh / H;
    const int h  = bh % H;
    const int q0 = blockIdx.x * BQ;
    const int vlen = valid[b];
    const float qscale = 0.125f * 1.4426950408889634f;   // scale * log2(e)

    const float* qbase = g_q + (size_t)b * S * D + (size_t)h * HD;
    const float* kbase = g_k + (size_t)b * S * D + (size_t)h * HD;
    const float* vbase = g_v + (size_t)b * S * D + (size_t)h * HD;

    // Stage Q tile
#pragma unroll
    for (int t = 0; t < 8; t++) {
        int idx = tid + t * 256;
        int row = idx >> 4;
        int c   = idx & 15;
        float4 tq = *(const float4*)(qbase + (size_t)(q0 + row) * D + c * 4);
        float* dq = &Qs[row * QP + c * 4];
        dq[0] = tq.x; dq[1] = tq.y; dq[2] = tq.z; dq[3] = tq.w;
    }
    // Preload K/V tile 0 into buffer 0
    {
#pragma unroll
        for (int t = 0; t < 4; t++) {
            int idx = tid + t * 256;
            int row = idx >> 4;
            int c   = idx & 15;
            uint32_t off = (uint32_t)(row * KP + c * 4) * 4;
            cp_async16(uKs + off, kbase + (size_t)row * D + c * 4);
            cp_async16(uVs + off, vbase + (size_t)row * D + c * 4);
        }
        cp_commit();
    }
    __syncthreads();   // Qs visible

    const int r0 = wid * 16;
    uint32_t qh[8][4], ql[8][4];
#pragma unroll
    for (int ks = 0; ks < 8; ks++) {
        const int k0 = ks * 8;
        float qf[4];
        qf[0] = qscale * Qs[(r0 + g) * QP + k0 + tg];
        qf[1] = qscale * Qs[(r0 + g + 8) * QP + k0 + tg];
        qf[2] = qscale * Qs[(r0 + g) * QP + k0 + tg + 4];
        qf[3] = qscale * Qs[(r0 + g + 8) * QP + k0 + tg + 4];
#pragma unroll
        for (int i = 0; i < 4; i++) {
            qh[ks][i] = f2tf32(qf[i]);
            ql[ks][i] = f2tf32(qf[i] - __uint_as_float(qh[ks][i]));
        }
    }

    float o[8][4];
#pragma unroll
    for (int ni = 0; ni < 8; ni++)
#pragma unroll
        for (int c = 0; c < 4; c++) o[ni][c] = 0.f;
    float m0 = -INFINITY, m1 = -INFINITY, l0 = 0.f, l1 = 0.f;

    const int nk = (vlen == 0) ? (S / BKT) : ((vlen + BKT - 1) / BKT);
    float* Pw = Ps + wid * 16 * PP;

    for (int kt = 0; kt < nk; kt++) {
        const int buf = kt % NKV;
        const int kr0 = kt * BKT;
        if (kt + 1 < nk) {
            const int nr0 = (kt + 1) * BKT;
            const uint32_t bo = (uint32_t)(((kt + 1) % NKV) * BKT * KP) * 4;
#pragma unroll
            for (int t = 0; t < 4; t++) {
                int idx = tid + t * 256;
                int row = idx >> 4;
                int c   = idx & 15;
                uint32_t off = bo + (uint32_t)(row * KP + c * 4) * 4;
                cp_async16(uKs + off, kbase + (size_t)(nr0 + row) * D + c * 4);
                cp_async16(uVs + off, vbase + (size_t)(nr0 + row) * D + c * 4);
            }
            cp_commit();
            asm volatile("cp.async.wait_group 1;" ::: "memory");
        } else {
            asm volatile("cp.async.wait_group 0;" ::: "memory");
        }
        __syncthreads();   // tile kt ready; bounds warp skew to 1 iteration

        const float* Kb = Ks + buf * BKT * KP;
        const float* Vb = Vs + buf * BKT * KP;

        // ---- S(log2) = (Q*qscale) @ K^T (2-MMA tf32 split) ----
        float sc[8][4];
#pragma unroll
        for (int ni = 0; ni < 8; ni++)
#pragma unroll
            for (int c = 0; c < 4; c++) sc[ni][c] = 0.f;

#pragma unroll
        for (int ks = 0; ks < 8; ks++) {
            const int k0 = ks * 8;
#pragma unroll
            for (int ni = 0; ni < 8; ni++) {
                const float* kr = &Kb[(ni * 8 + g) * KP + k0];
                uint32_t b0 = __float_as_uint(kr[tg]);
                uint32_t b1 = __float_as_uint(kr[tg + 4]);
                mma_tf32(sc[ni], qh[ks], b0, b1);
                mma_tf32(sc[ni], ql[ks], b0, b1);
            }
        }

        // ---- mask (boundary/empty tiles only) + online softmax (log2) ----
        if (kr0 + BKT > vlen) {
#pragma unroll
            for (int ni = 0; ni < 8; ni++) {
                int col = kr0 + ni * 8 + 2 * tg;
                bool v0 = col < vlen, v1 = (col + 1) < vlen;
                sc[ni][0] = v0 ? sc[ni][0] : MASK_VALUE;
                sc[ni][1] = v1 ? sc[ni][1] : MASK_VALUE;
                sc[ni][2] = v0 ? sc[ni][2] : MASK_VALUE;
                sc[ni][3] = v1 ? sc[ni][3] : MASK_VALUE;
            }
        }

        float mn0 = m0, mn1 = m1;
#pragma unroll
        for (int ni = 0; ni < 8; ni++) {
            mn0 = fmaxf(mn0, fmaxf(sc[ni][0], sc[ni][1]));
            mn1 = fmaxf(mn1, fmaxf(sc[ni][2], sc[ni][3]));
        }
        mn0 = fmaxf(mn0, __shfl_xor_sync(0xffffffffu, mn0, 1));
        mn0 = fmaxf(mn0, __shfl_xor_sync(0xffffffffu, mn0, 2));
        mn1 = fmaxf(mn1, __shfl_xor_sync(0xffffffffu, mn1, 1));
        mn1 = fmaxf(mn1, __shfl_xor_sync(0xffffffffu, mn1, 2));

        float a0 = ex2(m0 - mn0);
        float a1 = ex2(m1 - mn1);
        m0 = mn0; m1 = mn1;

        float rs0 = 0.f, rs1 = 0.f;
#pragma unroll
        for (int ni = 0; ni < 8; ni++) {
            float p0 = rnd_tf32(ex2(sc[ni][0] - mn0));
            float p1 = rnd_tf32(ex2(sc[ni][1] - mn0));
            float p2 = rnd_tf32(ex2(sc[ni][2] - mn1));
            float p3 = rnd_tf32(ex2(sc[ni][3] - mn1));
            rs0 += p0 + p1;
            rs1 += p2 + p3;
            *(float2*)(&Pw[g * PP + ni * 8 + 2 * tg])       = make_float2(p0, p1);
            *(float2*)(&Pw[(g + 8) * PP + ni * 8 + 2 * tg]) = make_float2(p2, p3);
        }
        rs0 += __shfl_xor_sync(0xffffffffu, rs0, 1);
        rs0 += __shfl_xor_sync(0xffffffffu, rs0, 2);
        rs1 += __shfl_xor_sync(0xffffffffu, rs1, 1);
        rs1 += __shfl_xor_sync(0xffffffffu, rs1, 2);
        l0 = l0 * a0 + rs0;
        l1 = l1 * a1 + rs1;

#pragma unroll
        for (int ni = 0; ni < 8; ni++) {
            o[ni][0] *= a0; o[ni][1] *= a0;
            o[ni][2] *= a1; o[ni][3] *= a1;
        }
        __syncwarp();

        // ---- O += P @ V (both tf32) ----
#pragma unroll
        for (int ks = 0; ks < 8; ks++) {
            const int k0 = ks * 8;
            uint32_t pa[4];
            pa[0] = __float_as_uint(Pw[g * PP + k0 + tg]);
            pa[1] = __float_as_uint(Pw[(g + 8) * PP + k0 + tg]);
            pa[2] = __float_as_uint(Pw[g * PP + k0 + tg + 4]);
            pa[3] = __float_as_uint(Pw[(g + 8) * PP + k0 + tg + 4]);
#pragma unroll
            for (int ni = 0; ni < 8; ni++) {
                uint32_t b0 = __float_as_uint(Vb[(k0 + tg) * KP + ni * 8 + g]);
                uint32_t b1 = __float_as_uint(Vb[(k0 + tg + 4) * KP + ni * 8 + g]);
                mma_tf32(o[ni], pa, b0, b1);
            }
        }
        __syncwarp();
        // no end-of-tile __syncthreads: 3-buffer rotation keeps the
        // next prefetch target disjoint from any in-use buffer
    }

    // Epilogue: normalize + round to tf32 (feeds gemm_out's raw loads)
    float inv0 = 1.f / l0, inv1 = 1.f / l1;
    int row0 = q0 + r0 + g;
#pragma unroll
    for (int ni = 0; ni < 8; ni++) {
        int col = h * HD + ni * 8 + 2 * tg;
        *(float2*)(&out[((size_t)b * S + row0) * D + col]) =
            make_float2(rnd_tf32(o[ni][0] * inv0), rnd_tf32(o[ni][1] * inv0));
        *(float2*)(&out[((size_t)b * S + row0 + 8) * D + col]) =
            make_float2(rnd_tf32(o[ni][2] * inv1), rnd_tf32(o[ni][3] * inv1));
    }
}

// ===========================================================================
// Launch
// ===========================================================================
extern "C" void kernel_launch(void* const* d_in, const int* in_sizes, int n_in,
                              void* d_out, int out_size)
{
    const float* Q  = (const float*)d_in[0];
    const float* K  = (const float*)d_in[1];
    const float* V  = (const float*)d_in[2];
    const int* valid = (const int*)d_in[3];
    const float* Wq = (const float*)d_in[4];
    const float* Wk = (const float*)d_in[5];
    const float* Wv = (const float*)d_in[6];
    const float* Wo = (const float*)d_in[7];
    float* out = (float*)d_out;

    float* ga;
    cudaGetSymbolAddress((void**)&ga, g_attn);

    cudaFuncSetAttribute(gemm_qkv, cudaFuncAttributeMaxDynamicSharedMemorySize,
                         GEMM_SMEM_BYTES);
    cudaFuncSetAttribute(gemm_out, cudaFuncAttributeMaxDynamicSharedMemorySize,
                         GEMM_SMEM_BYTES);
    cudaFuncSetAttribute(attn_mma, cudaFuncAttributeMaxDynamicSharedMemorySize,
                         AT_SMEM_BYTES);

    prep_acts<<<dim3(BSD / 4 / 256, 1, 3), 256>>>(Q, K, V);
    prep_w<<<dim3(D * D / 4 / 256, 1, 4), 256>>>(Wq, Wk, Wv, Wo);

    gemm_qkv<<<dim3(D / 128, (B * S) / 128, 3), 128, GEMM_SMEM_BYTES>>>();

    attn_mma<<<dim3(S / BQ, B * H), 256, AT_SMEM_BYTES>>>(valid, ga);

    gemm_out<<<dim3(D / 128, (B * S) / 128), 128, GEMM_SMEM_BYTES>>>(out);
}